// round 1
// baseline (speedup 1.0000x reference)
#include <cuda_runtime.h>
#include <cuda_bf16.h>

#define N_ATOM 131072
#define E_ATOM 524288
#define N_FRAG 32768
#define E_FRAG 131072
#define HID 256
#define HID4 64
#define FEAT 9

// ---------------- device scratch (allocation-free rule: __device__ globals) ----
__device__ float g_xa[(size_t)N_ATOM * HID];    // atom features after input proj
__device__ float g_tmpA[(size_t)N_ATOM * HID];  // atom-sized scratch (GEMM out)
__device__ float g_xf[(size_t)N_FRAG * HID];    // frag features
__device__ float g_tmpF[(size_t)N_FRAG * HID];  // frag-sized scratch
__device__ float g_ewA[E_ATOM];
__device__ float g_degA[N_ATOM];   // degree, then overwritten with deg^-1/2
__device__ float g_ewF[E_FRAG];
__device__ float g_degF[N_FRAG];
__device__ float g_cnt[N_FRAG];

// ---------------- helpers ----------------------------------------------------
__device__ __forceinline__ void red_add_v4(float* addr, float4 v) {
    asm volatile("red.global.add.v4.f32 [%0], {%1, %2, %3, %4};"
                 :: "l"(addr), "f"(v.x), "f"(v.y), "f"(v.z), "f"(v.w)
                 : "memory");
}

// ---------------- input projections (FEAT=9 -> HID=256) -----------------------
// one block per atom row; also seeds deg=1 (self loop)
__global__ __launch_bounds__(HID) void k_atom_in(
    const float* __restrict__ x_atom, const float* __restrict__ W1,
    const float* __restrict__ b1, const float* __restrict__ s0,
    float* __restrict__ xa, float* __restrict__ degA)
{
    __shared__ float xs[FEAT];
    int r = blockIdx.x, h = threadIdx.x;
    if (h < FEAT) xs[h] = x_atom[r * FEAT + h];
    __syncthreads();
    float s = b1[h] + s0[(size_t)r * HID + h];
#pragma unroll
    for (int f = 0; f < FEAT; f++) s += xs[f] * W1[f * HID + h];
    xa[(size_t)r * HID + h] = s;
    if (h == 0) degA[r] = 1.0f;
}

// one block per frag row; also zeroes pooling scratch + cnt, seeds deg=1
__global__ __launch_bounds__(HID) void k_frag_in(
    const float* __restrict__ frag_h, const float* __restrict__ W2,
    const float* __restrict__ b2,
    float* __restrict__ xf, float* __restrict__ tmpF,
    float* __restrict__ degF, float* __restrict__ cnt)
{
    __shared__ float xs[FEAT];
    int r = blockIdx.x, h = threadIdx.x;
    if (h < FEAT) xs[h] = frag_h[r * FEAT + h];
    __syncthreads();
    float s = b2[h];
#pragma unroll
    for (int f = 0; f < FEAT; f++) s += xs[f] * W2[f * HID + h];
    xf[(size_t)r * HID + h] = s;
    tmpF[(size_t)r * HID + h] = 0.0f;
    if (h == 0) { degF[r] = 1.0f; cnt[r] = 0.0f; }
}

// ---------------- edge prep: ew = 1-sigmoid(raw) = sigmoid(-raw); deg[dst]+=ew
__global__ void k_edge_prep(const int* __restrict__ ei,
                            const float* __restrict__ raw,
                            float* __restrict__ ew, float* __restrict__ deg, int E)
{
    int e = blockIdx.x * blockDim.x + threadIdx.x;
    if (e >= E) return;
    float w = 1.0f / (1.0f + __expf(raw[e]));
    ew[e] = w;
    atomicAdd(&deg[ei[E + e]], w);   // dst = row 1
}

__global__ void k_rsqrt(float* __restrict__ deg, int n)
{
    int i = blockIdx.x * blockDim.x + threadIdx.x;
    if (i < n) deg[i] = rsqrtf(deg[i]);   // deg >= 1 always (self loop)
}

// ---------------- generic [M,256]x[256,256] fp32 GEMM -------------------------
// MODE 0: C = A@B ; MODE 1: C = A@B + bias ; MODE 2: C = (A@B + bias)*alpha[row]
#define GBM 64
#define GBN 128
#define GBK 16
template <int MODE>
__global__ __launch_bounds__(256) void gemm256(
    const float* __restrict__ A, const float* __restrict__ B,
    const float* __restrict__ bias, const float* __restrict__ alpha,
    float* __restrict__ C, int M)
{
    __shared__ float As[GBK][GBM + 1];
    __shared__ float Bs[GBK][GBN];
    int tid = threadIdx.x;
    int by = blockIdx.x, bx = blockIdx.y;
    int tx = tid & 31, ty = tid >> 5;
    int row0 = by * GBM, col0 = bx * GBN;

    int ar = tid >> 2;           // 0..63
    int ac = (tid & 3) * 4;      // 0,4,8,12
    int br = tid >> 5;           // 0..7
    int bc = (tid & 31) * 4;     // 0..124
    const float* Aptr = A + ((size_t)(row0 + ar)) * HID + ac;
    const float* Bptr = B + (size_t)br * HID + col0 + bc;

    float acc[8][4];
#pragma unroll
    for (int i = 0; i < 8; i++)
#pragma unroll
        for (int j = 0; j < 4; j++) acc[i][j] = 0.0f;

    for (int k0 = 0; k0 < HID; k0 += GBK) {
        float4 av = *(const float4*)(Aptr + k0);
        As[ac + 0][ar] = av.x; As[ac + 1][ar] = av.y;
        As[ac + 2][ar] = av.z; As[ac + 3][ar] = av.w;
        float4 bv0 = *(const float4*)(Bptr + (size_t)k0 * HID);
        float4 bv1 = *(const float4*)(Bptr + (size_t)(k0 + 8) * HID);
        *(float4*)&Bs[br][bc] = bv0;
        *(float4*)&Bs[br + 8][bc] = bv1;
        __syncthreads();
#pragma unroll
        for (int k = 0; k < GBK; k++) {
            float a[8];
#pragma unroll
            for (int i = 0; i < 8; i++) a[i] = As[k][ty * 8 + i];
            float4 b = *(float4*)&Bs[k][tx * 4];
#pragma unroll
            for (int i = 0; i < 8; i++) {
                acc[i][0] += a[i] * b.x; acc[i][1] += a[i] * b.y;
                acc[i][2] += a[i] * b.z; acc[i][3] += a[i] * b.w;
            }
        }
        __syncthreads();
    }

    int crow = row0 + ty * 8;
    int ccol = col0 + tx * 4;
    float4 bb = make_float4(0.f, 0.f, 0.f, 0.f);
    if (MODE >= 1) bb = *(const float4*)(bias + ccol);
#pragma unroll
    for (int i = 0; i < 8; i++) {
        float4 v = make_float4(acc[i][0] + bb.x, acc[i][1] + bb.y,
                               acc[i][2] + bb.z, acc[i][3] + bb.w);
        if (MODE == 2) {
            float al = alpha[crow + i];
            v.x *= al; v.y *= al; v.z *= al; v.w *= al;
        }
        *(float4*)(C + (size_t)(crow + i) * HID + ccol) = v;
    }
}

// ---------------- GCN aggregation --------------------------------------------
// acc[i,:] = xw[i,:] * dinv[i]^2   (self-loop message, also overwrites poison)
__global__ void k_acc_init(const float* __restrict__ xw,
                           const float* __restrict__ dinv,
                           float* __restrict__ acc, int n)
{
    int i = blockIdx.x * blockDim.x + threadIdx.x;
    if (i >= n * HID4) return;
    int r = i >> 6;
    float d = dinv[r]; d = d * d;
    float4 v = ((const float4*)xw)[i];
    v.x *= d; v.y *= d; v.z *= d; v.w *= d;
    ((float4*)acc)[i] = v;
}

// per edge: acc[dst,:] += dinv[src]*ew*dinv[dst] * xw[src,:]   (64 thr/edge)
__global__ __launch_bounds__(256) void k_scatter(
    const int* __restrict__ ei, const float* __restrict__ ew,
    const float* __restrict__ dinv, const float* __restrict__ xw,
    float* __restrict__ acc, int E)
{
    int e = blockIdx.x * 4 + (threadIdx.x >> 6);
    int j = threadIdx.x & 63;
    if (e >= E) return;
    int s = ei[e], d = ei[E + e];
    float nrm = dinv[s] * ew[e] * dinv[d];
    float4 v = ((const float4*)(xw + (size_t)s * HID))[j];
    v.x *= nrm; v.y *= nrm; v.z *= nrm; v.w *= nrm;
    red_add_v4(acc + (size_t)d * HID + (j << 2), v);
}

// acc = relu(acc + bias)  (in place)
__global__ void k_bias_relu(float* __restrict__ acc,
                            const float* __restrict__ bias, int n)
{
    int i = blockIdx.x * blockDim.x + threadIdx.x;
    if (i >= n * HID4) return;
    float4 v = ((float4*)acc)[i];
    float4 b = ((const float4*)bias)[i & 63];
    v.x = fmaxf(v.x + b.x, 0.f); v.y = fmaxf(v.y + b.y, 0.f);
    v.z = fmaxf(v.z + b.z, 0.f); v.w = fmaxf(v.w + b.w, 0.f);
    ((float4*)acc)[i] = v;
}

// ---------------- atom -> frag pooling ---------------------------------------
__global__ __launch_bounds__(256) void k_pool(
    const int* __restrict__ a2f, const float* __restrict__ xp,
    float* __restrict__ fsum, float* __restrict__ cnt, int n)
{
    int a = blockIdx.x * 4 + (threadIdx.x >> 6);
    int j = threadIdx.x & 63;
    if (a >= n) return;
    int f = a2f[a];
    float4 v = ((const float4*)(xp + (size_t)a * HID))[j];
    red_add_v4(fsum + (size_t)f * HID + (j << 2), v);
    if (j == 0) atomicAdd(&cnt[f], 1.0f);
}

// xf += fsum / max(cnt,1)
__global__ void k_frag_combine(float* __restrict__ xf,
                               const float* __restrict__ fsum,
                               const float* __restrict__ cnt, int n)
{
    int i = blockIdx.x * blockDim.x + threadIdx.x;
    if (i >= n * HID4) return;
    int r = i >> 6;
    float inv = 1.0f / fmaxf(cnt[r], 1.0f);
    float4 v = ((float4*)xf)[i];
    float4 t = ((const float4*)fsum)[i];
    v.x += t.x * inv; v.y += t.y * inv; v.z += t.z * inv; v.w += t.w * inv;
    ((float4*)xf)[i] = v;
}

// ---------------- frag -> atom broadcast: xa += xfp[a2f[a]] * alpha[a] --------
__global__ __launch_bounds__(256) void k_final(
    const int* __restrict__ a2f, const float* __restrict__ alpha,
    const float* __restrict__ xfp, float* __restrict__ xa, int n)
{
    int a = blockIdx.x * 4 + (threadIdx.x >> 6);
    int j = threadIdx.x & 63;
    if (a >= n) return;
    int f = a2f[a];
    float al = alpha[a];
    float4 v = ((float4*)(xa + (size_t)a * HID))[j];
    float4 p = ((const float4*)(xfp + (size_t)f * HID))[j];
    v.x += p.x * al; v.y += p.y * al; v.z += p.z * al; v.w += p.w * al;
    ((float4*)(xa + (size_t)a * HID))[j] = v;
}

// ---------------- host orchestration -----------------------------------------
extern "C" void kernel_launch(void* const* d_in, const int* in_sizes, int n_in,
                              void* d_out, int out_size)
{
    const float* x_atom  = (const float*)d_in[0];
    const int*   eiA     = (const int*)  d_in[1];
    const float* frag_h  = (const float*)d_in[2];
    const int*   eiF     = (const int*)  d_in[3];
    const int*   a2f     = (const int*)  d_in[4];
    const float* s0      = (const float*)d_in[5];
    const float* alpha   = (const float*)d_in[6];
    const float* curv    = (const float*)d_in[7];
    const float* fewraw  = (const float*)d_in[8];
    const float* W1      = (const float*)d_in[9];
    const float* b1      = (const float*)d_in[10];
    const float* W2      = (const float*)d_in[11];
    const float* b2      = (const float*)d_in[12];
    const float* Wg1     = (const float*)d_in[13];
    const float* bg1     = (const float*)d_in[14];
    const float* Wg2     = (const float*)d_in[15];
    const float* bg2     = (const float*)d_in[16];
    const float* Wa2f    = (const float*)d_in[17];
    const float* ba2f    = (const float*)d_in[18];
    const float* Wf2a    = (const float*)d_in[19];
    const float* bf2a    = (const float*)d_in[20];

    float* out_xa = (float*)d_out;
    float* out_xf = out_xa + (size_t)N_ATOM * HID;

    float *xa, *tmpA, *xf, *tmpF, *ewA, *degA, *ewF, *degF, *cnt;
    cudaGetSymbolAddress((void**)&xa,   g_xa);
    cudaGetSymbolAddress((void**)&tmpA, g_tmpA);
    cudaGetSymbolAddress((void**)&xf,   g_xf);
    cudaGetSymbolAddress((void**)&tmpF, g_tmpF);
    cudaGetSymbolAddress((void**)&ewA,  g_ewA);
    cudaGetSymbolAddress((void**)&degA, g_degA);
    cudaGetSymbolAddress((void**)&ewF,  g_ewF);
    cudaGetSymbolAddress((void**)&degF, g_degF);
    cudaGetSymbolAddress((void**)&cnt,  g_cnt);

    // 1. input projections (also seed deg=1, zero pooling scratch)
    k_atom_in<<<N_ATOM, HID>>>(x_atom, W1, b1, s0, xa, degA);
    k_frag_in<<<N_FRAG, HID>>>(frag_h, W2, b2, xf, tmpF, degF, cnt);

    // 2. atom edge weights + degrees, dinv
    k_edge_prep<<<E_ATOM / 256, 256>>>(eiA, curv, ewA, degA, E_ATOM);
    k_rsqrt<<<N_ATOM / 256, 256>>>(degA, N_ATOM);

    // 3. atom GCN: tmpA = xa @ Wg1; acc(out_xa) = selfloop + edge scatter; relu+bias
    gemm256<0><<<dim3(N_ATOM / GBM, HID / GBN), 256>>>(xa, Wg1, nullptr, nullptr, tmpA, N_ATOM);
    k_acc_init<<<N_ATOM * HID4 / 256, 256>>>(tmpA, degA, out_xa, N_ATOM);
    k_scatter<<<E_ATOM / 4, 256>>>(eiA, ewA, degA, tmpA, out_xa, E_ATOM);
    k_bias_relu<<<N_ATOM * HID4 / 256, 256>>>(out_xa, bg1, N_ATOM);
    // out_xa now holds xa_relu

    // 4. atom->frag pooling: tmpA = (xa_relu @ Wa2f + ba2f) * alpha
    gemm256<2><<<dim3(N_ATOM / GBM, HID / GBN), 256>>>(out_xa, Wa2f, ba2f, alpha, tmpA, N_ATOM);
    k_pool<<<N_ATOM / 4, 256>>>(a2f, tmpA, tmpF, cnt, N_ATOM);
    k_frag_combine<<<N_FRAG * HID4 / 256, 256>>>(xf, tmpF, cnt, N_FRAG);

    // 5. frag edge weights + degrees, dinv
    k_edge_prep<<<E_FRAG / 256, 256>>>(eiF, fewraw, ewF, degF, E_FRAG);
    k_rsqrt<<<N_FRAG / 256, 256>>>(degF, N_FRAG);

    // 6. frag GCN
    gemm256<0><<<dim3(N_FRAG / GBM, HID / GBN), 256>>>(xf, Wg2, nullptr, nullptr, tmpF, N_FRAG);
    k_acc_init<<<N_FRAG * HID4 / 256, 256>>>(tmpF, degF, out_xf, N_FRAG);
    k_scatter<<<E_FRAG / 4, 256>>>(eiF, ewF, degF, tmpF, out_xf, E_FRAG);
    k_bias_relu<<<N_FRAG * HID4 / 256, 256>>>(out_xf, bg2, N_FRAG);
    // out_xf now holds final x_frag

    // 7. frag->atom broadcast: tmpF = x_frag @ Wf2a + bf2a; xa += tmpF[a2f]*alpha
    gemm256<1><<<dim3(N_FRAG / GBM, HID / GBN), 256>>>(out_xf, Wf2a, bf2a, nullptr, tmpF, N_FRAG);
    k_final<<<N_ATOM / 4, 256>>>(a2f, alpha, tmpF, out_xa, N_ATOM);
}

// round 6
// speedup vs baseline: 1.4159x; 1.4159x over previous
#include <cuda_runtime.h>
#include <cuda_bf16.h>

#define N_ATOM 131072
#define E_ATOM 524288
#define N_FRAG 32768
#define E_FRAG 131072
#define HID 256
#define HID4 64
#define FEAT 9

// ================= device scratch (no allocs allowed) ========================
__device__ float g_tmpA[(size_t)N_ATOM * HID];  // atom-sized GEMM output
__device__ float g_tmpF[(size_t)N_FRAG * HID];  // frag-sized GEMM output / pool
__device__ float g_xf[(size_t)N_FRAG * HID];    // frag input projection (fp32)
__device__ float g_ewA[E_ATOM];
__device__ float g_degA[N_ATOM];
__device__ float g_ewF[E_FRAG];
__device__ float g_degF[N_FRAG];
__device__ float g_cnt[N_FRAG];
// bf16x3 split operand buffers
__device__ __nv_bfloat16 g_ah[(size_t)N_ATOM * HID];
__device__ __nv_bfloat16 g_am[(size_t)N_ATOM * HID];
__device__ __nv_bfloat16 g_fh[(size_t)N_FRAG * HID];
__device__ __nv_bfloat16 g_fm[(size_t)N_FRAG * HID];
// transposed+split weights: [4][256][256] (0=Wg1, 1=Wa2f, 2=Wg2, 3=Wf2a)
__device__ __nv_bfloat16 g_wth[4 * HID * HID];
__device__ __nv_bfloat16 g_wtm[4 * HID * HID];

// ================= PTX helpers ===============================================
__device__ __forceinline__ void red_add_v4(float* addr, float4 v) {
    asm volatile("red.global.add.v4.f32 [%0], {%1, %2, %3, %4};"
                 :: "l"(addr), "f"(v.x), "f"(v.y), "f"(v.z), "f"(v.w)
                 : "memory");
}
__device__ __forceinline__ unsigned smem_u32(const void* p) {
    unsigned a;
    asm("{ .reg .u64 t; cvta.to.shared.u64 t, %1; cvt.u32.u64 %0, t; }"
        : "=r"(a) : "l"(p));
    return a;
}
#define LDSM4(r, addr) \
    asm volatile("ldmatrix.sync.aligned.m8n8.x4.shared.b16 {%0,%1,%2,%3}, [%4];" \
        : "=r"((r)[0]), "=r"((r)[1]), "=r"((r)[2]), "=r"((r)[3]) : "r"(addr))

#define MMA16816(c, a, b0, b1) \
    asm volatile("mma.sync.aligned.m16n8k16.row.col.f32.bf16.bf16.f32 " \
        "{%0,%1,%2,%3}, {%4,%5,%6,%7}, {%8,%9}, {%0,%1,%2,%3};" \
        : "+f"((c)[0]), "+f"((c)[1]), "+f"((c)[2]), "+f"((c)[3]) \
        : "r"((a)[0]), "r"((a)[1]), "r"((a)[2]), "r"((a)[3]), "r"(b0), "r"(b1))

static __device__ __forceinline__ unsigned sw128(unsigned b) {
    return b ^ ((b >> 3) & 0x70);
}

__device__ __forceinline__ void split2(float x, __nv_bfloat16& h, __nv_bfloat16& m) {
    h = __float2bfloat16_rn(x);
    m = __float2bfloat16_rn(x - __bfloat162float(h));
}

// ============ mma.sync bf16x3 GEMM: C[M,256] = A[M,256] @ W[256,256] =========
// A split bf16 (hi+mid), W transposed+split ([N][K] bf16 = .col operand).
// MODE 0: C = A@W ; MODE 1: +bias ; MODE 2: (A@W + bias) * alpha[row]
// SELF 1: also Cacc = C * dinv[row]^2 (GCN self-loop init)
// Block tile: 64(M) x 128(N), BK = 64, static 48KB smem, single-buffered.
// 8 warps: wm = wid&1 (32-row band), wn = wid>>1 (32-col band).
template <int MODE, int SELF>
__global__ __launch_bounds__(256, 2) void gemm_mma(
    const __nv_bfloat16* __restrict__ Ahi, const __nv_bfloat16* __restrict__ Amid,
    const __nv_bfloat16* __restrict__ Bhi, const __nv_bfloat16* __restrict__ Bmid,
    const float* __restrict__ bias, const float* __restrict__ alpha,
    const float* __restrict__ dinv, float* __restrict__ Cacc,
    float* __restrict__ C)
{
    __shared__ __align__(16) unsigned char sAh[64 * 128];
    __shared__ __align__(16) unsigned char sAm[64 * 128];
    __shared__ __align__(16) unsigned char sBh[128 * 128];
    __shared__ __align__(16) unsigned char sBm[128 * 128];

    int t = threadIdx.x, wid = t >> 5, lane = t & 31;
    int wm = wid & 1, wn = wid >> 1;
    int row0A = blockIdx.x * 64;
    int n0B = blockIdx.y * 128;

    unsigned uAh = smem_u32(sAh), uAm = smem_u32(sAm);
    unsigned uBh = smem_u32(sBh), uBm = smem_u32(sBm);

    int rl = lane & 15;
    unsigned cl = (lane & 16);

    float c[2][4][4];
#pragma unroll
    for (int i = 0; i < 2; i++)
#pragma unroll
        for (int j = 0; j < 4; j++)
#pragma unroll
            for (int q = 0; q < 4; q++) c[i][j][q] = 0.0f;

#pragma unroll 1
    for (int ch = 0; ch < 4; ch++) {
        int k0 = ch * 64;
        __syncthreads();   // previous compute done before overwrite
        // ---- load A tiles: 64 rows x 64 bf16 (128B rows), hi + mid ----
#pragma unroll
        for (int i = 0; i < 2; i++) {
            int idx = i * 256 + t;
            int r = idx >> 3, c8 = idx & 7;
            unsigned sw = sw128((unsigned)(r * 128 + c8 * 16));
            *(float4*)(sAh + sw) =
                *(const float4*)(Ahi + (size_t)(row0A + r) * HID + k0 + c8 * 8);
            *(float4*)(sAm + sw) =
                *(const float4*)(Amid + (size_t)(row0A + r) * HID + k0 + c8 * 8);
        }
        // ---- load B tiles: 128 rows(N) x 64 bf16, hi + mid ----
#pragma unroll
        for (int i = 0; i < 4; i++) {
            int idx = i * 256 + t;
            int r = idx >> 3, c8 = idx & 7;
            unsigned sw = sw128((unsigned)(r * 128 + c8 * 16));
            *(float4*)(sBh + sw) =
                *(const float4*)(Bhi + (size_t)(n0B + r) * HID + k0 + c8 * 8);
            *(float4*)(sBm + sw) =
                *(const float4*)(Bmid + (size_t)(n0B + r) * HID + k0 + c8 * 8);
        }
        __syncthreads();

        // ---- compute: 4 k16 steps ----
#pragma unroll
        for (int s = 0; s < 4; s++) {
            unsigned kb = s * 32;
            unsigned ah[2][4], am[2][4], bh[2][4], bm[2][4];
#pragma unroll
            for (int mt = 0; mt < 2; mt++) {
                unsigned off = sw128((unsigned)((wm * 32 + mt * 16 + rl) * 128) + kb + cl);
                LDSM4(ah[mt], uAh + off);
                LDSM4(am[mt], uAm + off);
            }
#pragma unroll
            for (int ng = 0; ng < 2; ng++) {
                unsigned off = sw128((unsigned)((wn * 32 + ng * 16 + rl) * 128) + kb + cl);
                LDSM4(bh[ng], uBh + off);
                LDSM4(bm[ng], uBm + off);
            }
#pragma unroll
            for (int mt = 0; mt < 2; mt++)
#pragma unroll
                for (int nt = 0; nt < 4; nt++) {
                    int ng = nt >> 1, sel = nt & 1;
                    MMA16816(c[mt][nt], ah[mt], bh[ng][sel], bh[ng][sel + 2]);
                    MMA16816(c[mt][nt], ah[mt], bm[ng][sel], bm[ng][sel + 2]);
                    MMA16816(c[mt][nt], am[mt], bh[ng][sel], bh[ng][sel + 2]);
                }
        }
    }

    // ---- epilogue ----
    int mwarp = row0A + wm * 32;
    int col0 = n0B + wn * 32;
    int gc = (lane & 3) * 2;
#pragma unroll
    for (int mt = 0; mt < 2; mt++) {
#pragma unroll
        for (int h = 0; h < 2; h++) {
            int row = mwarp + mt * 16 + (lane >> 2) + h * 8;
            float al = 1.0f, d2 = 0.0f;
            if (MODE == 2) al = alpha[row];
            if (SELF) { d2 = dinv[row]; d2 = d2 * d2; }
#pragma unroll
            for (int nt = 0; nt < 4; nt++) {
                int col = col0 + nt * 8 + gc;
                float v0 = c[mt][nt][h * 2 + 0];
                float v1 = c[mt][nt][h * 2 + 1];
                if (MODE >= 1) {
                    float2 bb = *(const float2*)(bias + col);
                    v0 += bb.x; v1 += bb.y;
                }
                if (MODE == 2) { v0 *= al; v1 *= al; }
                *(float2*)(C + (size_t)row * HID + col) = make_float2(v0, v1);
                if (SELF)
                    *(float2*)(Cacc + (size_t)row * HID + col) =
                        make_float2(v0 * d2, v1 * d2);
            }
        }
    }
}

// ================= weight prep: Bt[n][k] = split(W[k][n]) ====================
__global__ void k_wprep(const float* __restrict__ W,
                        __nv_bfloat16* __restrict__ Bh,
                        __nv_bfloat16* __restrict__ Bm)
{
    int n = blockIdx.x, k = threadIdx.x;
    float x = W[k * HID + n];
    __nv_bfloat16 h, m;
    split2(x, h, m);
    Bh[n * HID + k] = h;
    Bm[n * HID + k] = m;
}

// ================= input projections =========================================
__global__ __launch_bounds__(HID) void k_atom_in(
    const float* __restrict__ x_atom, const float* __restrict__ W1,
    const float* __restrict__ b1, const float* __restrict__ s0,
    __nv_bfloat16* __restrict__ oh, __nv_bfloat16* __restrict__ om,
    float* __restrict__ degA)
{
    __shared__ float xs[FEAT];
    int r = blockIdx.x, h = threadIdx.x;
    if (h < FEAT) xs[h] = x_atom[r * FEAT + h];
    __syncthreads();
    float s = b1[h] + s0[(size_t)r * HID + h];
#pragma unroll
    for (int f = 0; f < FEAT; f++) s += xs[f] * W1[f * HID + h];
    __nv_bfloat16 hi, mi;
    split2(s, hi, mi);
    oh[(size_t)r * HID + h] = hi;
    om[(size_t)r * HID + h] = mi;
    if (h == 0) degA[r] = 1.0f;
}

__global__ __launch_bounds__(HID) void k_frag_in(
    const float* __restrict__ frag_h, const float* __restrict__ W2,
    const float* __restrict__ b2,
    float* __restrict__ xf, float* __restrict__ tmpF,
    float* __restrict__ degF, float* __restrict__ cnt)
{
    __shared__ float xs[FEAT];
    int r = blockIdx.x, h = threadIdx.x;
    if (h < FEAT) xs[h] = frag_h[r * FEAT + h];
    __syncthreads();
    float s = b2[h];
#pragma unroll
    for (int f = 0; f < FEAT; f++) s += xs[f] * W2[f * HID + h];
    xf[(size_t)r * HID + h] = s;
    tmpF[(size_t)r * HID + h] = 0.0f;
    if (h == 0) { degF[r] = 1.0f; cnt[r] = 0.0f; }
}

// ================= edge prep =================================================
__global__ void k_edge_prep(const int* __restrict__ ei,
                            const float* __restrict__ raw,
                            float* __restrict__ ew, float* __restrict__ deg, int E)
{
    int e = blockIdx.x * blockDim.x + threadIdx.x;
    if (e >= E) return;
    float w = 1.0f / (1.0f + __expf(raw[e]));
    ew[e] = w;
    atomicAdd(&deg[ei[E + e]], w);
}

__global__ void k_rsqrt(float* __restrict__ deg, int n)
{
    int i = blockIdx.x * blockDim.x + threadIdx.x;
    if (i < n) deg[i] = rsqrtf(deg[i]);
}

// ================= GCN edge scatter ==========================================
__global__ __launch_bounds__(256) void k_scatter(
    const int* __restrict__ ei, const float* __restrict__ ew,
    const float* __restrict__ dinv, const float* __restrict__ xw,
    float* __restrict__ acc, int E)
{
    int e = blockIdx.x * 4 + (threadIdx.x >> 6);
    int j = threadIdx.x & 63;
    if (e >= E) return;
    int s = ei[e], d = ei[E + e];
    float nrm = dinv[s] * ew[e] * dinv[d];
    float4 v = ((const float4*)(xw + (size_t)s * HID))[j];
    v.x *= nrm; v.y *= nrm; v.z *= nrm; v.w *= nrm;
    red_add_v4(acc + (size_t)d * HID + (j << 2), v);
}

// acc = relu(acc + bias), also emit split bf16 for next GEMM
__global__ void k_bias_relu(float* __restrict__ acc, const float* __restrict__ bias,
                            __nv_bfloat16* __restrict__ oh,
                            __nv_bfloat16* __restrict__ om, int n)
{
    int i = blockIdx.x * blockDim.x + threadIdx.x;
    if (i >= n * HID4) return;
    float4 v = ((float4*)acc)[i];
    float4 b = ((const float4*)bias)[i & 63];
    v.x = fmaxf(v.x + b.x, 0.f); v.y = fmaxf(v.y + b.y, 0.f);
    v.z = fmaxf(v.z + b.z, 0.f); v.w = fmaxf(v.w + b.w, 0.f);
    ((float4*)acc)[i] = v;
    __nv_bfloat16 h0, m0, h1, m1, h2, m2, h3, m3;
    split2(v.x, h0, m0); split2(v.y, h1, m1);
    split2(v.z, h2, m2); split2(v.w, h3, m3);
    __nv_bfloat162* ph = (__nv_bfloat162*)(oh + (size_t)i * 4);
    __nv_bfloat162* pm = (__nv_bfloat162*)(om + (size_t)i * 4);
    ph[0] = __nv_bfloat162(h0, h1); ph[1] = __nv_bfloat162(h2, h3);
    pm[0] = __nv_bfloat162(m0, m1); pm[1] = __nv_bfloat162(m2, m3);
}

// ================= atom -> frag pooling ======================================
__global__ __launch_bounds__(256) void k_pool(
    const int* __restrict__ a2f, const float* __restrict__ xp,
    float* __restrict__ fsum, float* __restrict__ cnt, int n)
{
    int a = blockIdx.x * 4 + (threadIdx.x >> 6);
    int j = threadIdx.x & 63;
    if (a >= n) return;
    int f = a2f[a];
    float4 v = ((const float4*)(xp + (size_t)a * HID))[j];
    red_add_v4(fsum + (size_t)f * HID + (j << 2), v);
    if (j == 0) atomicAdd(&cnt[f], 1.0f);
}

// xf + fsum/max(cnt,1) -> split bf16 (GEMM3 input)
__global__ void k_frag_combine(const float* __restrict__ xf,
                               const float* __restrict__ fsum,
                               const float* __restrict__ cnt,
                               __nv_bfloat16* __restrict__ oh,
                               __nv_bfloat16* __restrict__ om, int n)
{
    int i = blockIdx.x * blockDim.x + threadIdx.x;
    if (i >= n * HID4) return;
    int r = i >> 6;
    float inv = 1.0f / fmaxf(cnt[r], 1.0f);
    float4 v = ((const float4*)xf)[i];
    float4 t = ((const float4*)fsum)[i];
    v.x += t.x * inv; v.y += t.y * inv; v.z += t.z * inv; v.w += t.w * inv;
    __nv_bfloat16 h0, m0, h1, m1, h2, m2, h3, m3;
    split2(v.x, h0, m0); split2(v.y, h1, m1);
    split2(v.z, h2, m2); split2(v.w, h3, m3);
    __nv_bfloat162* ph = (__nv_bfloat162*)(oh + (size_t)i * 4);
    __nv_bfloat162* pm = (__nv_bfloat162*)(om + (size_t)i * 4);
    ph[0] = __nv_bfloat162(h0, h1); ph[1] = __nv_bfloat162(h2, h3);
    pm[0] = __nv_bfloat162(m0, m1); pm[1] = __nv_bfloat162(m2, m3);
}

// ================= frag -> atom broadcast ====================================
__global__ __launch_bounds__(256) void k_final(
    const int* __restrict__ a2f, const float* __restrict__ alpha,
    const float* __restrict__ xfp, float* __restrict__ xa, int n)
{
    int a = blockIdx.x * 4 + (threadIdx.x >> 6);
    int j = threadIdx.x & 63;
    if (a >= n) return;
    int f = a2f[a];
    float al = alpha[a];
    float4 v = ((float4*)(xa + (size_t)a * HID))[j];
    float4 p = ((const float4*)(xfp + (size_t)f * HID))[j];
    v.x += p.x * al; v.y += p.y * al; v.z += p.z * al; v.w += p.w * al;
    ((float4*)(xa + (size_t)a * HID))[j] = v;
}

// ================= host orchestration ========================================
extern "C" void kernel_launch(void* const* d_in, const int* in_sizes, int n_in,
                              void* d_out, int out_size)
{
    const float* x_atom  = (const float*)d_in[0];
    const int*   eiA     = (const int*)  d_in[1];
    const float* frag_h  = (const float*)d_in[2];
    const int*   eiF     = (const int*)  d_in[3];
    const int*   a2f     = (const int*)  d_in[4];
    const float* s0      = (const float*)d_in[5];
    const float* alpha   = (const float*)d_in[6];
    const float* curv    = (const float*)d_in[7];
    const float* fewraw  = (const float*)d_in[8];
    const float* W1      = (const float*)d_in[9];
    const float* b1      = (const float*)d_in[10];
    const float* W2      = (const float*)d_in[11];
    const float* b2      = (const float*)d_in[12];
    const float* Wg1     = (const float*)d_in[13];
    const float* bg1     = (const float*)d_in[14];
    const float* Wg2     = (const float*)d_in[15];
    const float* bg2     = (const float*)d_in[16];
    const float* Wa2f    = (const float*)d_in[17];
    const float* ba2f    = (const float*)d_in[18];
    const float* Wf2a    = (const float*)d_in[19];
    const float* bf2a    = (const float*)d_in[20];

    float* out_xa = (float*)d_out;
    float* out_xf = out_xa + (size_t)N_ATOM * HID;

    float *tmpA, *tmpF, *xf, *ewA, *degA, *ewF, *degF, *cnt;
    __nv_bfloat16 *ah, *am, *fh, *fm, *wth, *wtm;
    cudaGetSymbolAddress((void**)&tmpA, g_tmpA);
    cudaGetSymbolAddress((void**)&tmpF, g_tmpF);
    cudaGetSymbolAddress((void**)&xf,   g_xf);
    cudaGetSymbolAddress((void**)&ewA,  g_ewA);
    cudaGetSymbolAddress((void**)&degA, g_degA);
    cudaGetSymbolAddress((void**)&ewF,  g_ewF);
    cudaGetSymbolAddress((void**)&degF, g_degF);
    cudaGetSymbolAddress((void**)&cnt,  g_cnt);
    cudaGetSymbolAddress((void**)&ah,   g_ah);
    cudaGetSymbolAddress((void**)&am,   g_am);
    cudaGetSymbolAddress((void**)&fh,   g_fh);
    cudaGetSymbolAddress((void**)&fm,   g_fm);
    cudaGetSymbolAddress((void**)&wth,  g_wth);
    cudaGetSymbolAddress((void**)&wtm,  g_wtm);

    // 0. weight transpose + split
    k_wprep<<<HID, HID>>>(Wg1,  wth + 0 * HID * HID, wtm + 0 * HID * HID);
    k_wprep<<<HID, HID>>>(Wa2f, wth + 1 * HID * HID, wtm + 1 * HID * HID);
    k_wprep<<<HID, HID>>>(Wg2,  wth + 2 * HID * HID, wtm + 2 * HID * HID);
    k_wprep<<<HID, HID>>>(Wf2a, wth + 3 * HID * HID, wtm + 3 * HID * HID);

    // 1. input projections (emit split operands; seed deg; zero pool scratch)
    k_atom_in<<<N_ATOM, HID>>>(x_atom, W1, b1, s0, ah, am, degA);
    k_frag_in<<<N_FRAG, HID>>>(frag_h, W2, b2, xf, tmpF, degF, cnt);

    // 2. atom edge weights + degrees
    k_edge_prep<<<E_ATOM / 256, 256>>>(eiA, curv, ewA, degA, E_ATOM);
    k_rsqrt<<<N_ATOM / 256, 256>>>(degA, N_ATOM);

    // 3. atom GCN: GEMM writes tmpA (raw) + out_xa (self-loop scaled)
    gemm_mma<0, 1><<<dim3(N_ATOM / 64, 2), 256>>>(
        ah, am, wth, wtm, nullptr, nullptr, degA, out_xa, tmpA);
    k_scatter<<<E_ATOM / 4, 256>>>(eiA, ewA, degA, tmpA, out_xa, E_ATOM);
    k_bias_relu<<<N_ATOM * HID4 / 256, 256>>>(out_xa, bg1, ah, am, N_ATOM);

    // 4. atom->frag pooling
    gemm_mma<2, 0><<<dim3(N_ATOM / 64, 2), 256>>>(
        ah, am, wth + 1 * HID * HID, wtm + 1 * HID * HID, ba2f, alpha,
        nullptr, nullptr, tmpA);
    k_pool<<<N_ATOM / 4, 256>>>(a2f, tmpA, tmpF, cnt, N_ATOM);
    k_frag_combine<<<N_FRAG * HID4 / 256, 256>>>(xf, tmpF, cnt, fh, fm, N_FRAG);

    // 5. frag edge weights + degrees
    k_edge_prep<<<E_FRAG / 256, 256>>>(eiF, fewraw, ewF, degF, E_FRAG);
    k_rsqrt<<<N_FRAG / 256, 256>>>(degF, N_FRAG);

    // 6. frag GCN
    gemm_mma<0, 1><<<dim3(N_FRAG / 64, 2), 256>>>(
        fh, fm, wth + 2 * HID * HID, wtm + 2 * HID * HID, nullptr, nullptr,
        degF, out_xf, tmpF);
    k_scatter<<<E_FRAG / 4, 256>>>(eiF, ewF, degF, tmpF, out_xf, E_FRAG);
    k_bias_relu<<<N_FRAG * HID4 / 256, 256>>>(out_xf, bg2, fh, fm, N_FRAG);

    // 7. frag -> atom broadcast
    gemm_mma<1, 0><<<dim3(N_FRAG / 64, 2), 256>>>(
        fh, fm, wth + 3 * HID * HID, wtm + 3 * HID * HID, bf2a, nullptr,
        nullptr, nullptr, tmpF);
    k_final<<<N_ATOM / 4, 256>>>(a2f, alpha, tmpF, out_xa, N_ATOM);
}